// round 4
// baseline (speedup 1.0000x reference)
#include <cuda_runtime.h>

// Problem shapes (fixed by the dataset)
#define BATCH 4
#define HEADS 16
#define SEQ   2048
#define DH    64       // head dim
#define BM    128      // query rows per CTA (= threads per CTA, 1 row/thread)
#define BN    32       // key/value tile size
#define NT    128      // threads per CTA
#define NTILES (SEQ / BN)

// Flash attention, fp32, one thread owns one query row.
//   - K/V tiles double-buffered in SMEM; tile t+1 is prefetched into registers
//     at the top of iteration t (LDG latency hidden behind the whole tile's
//     compute) and stored to the alternate buffer just before the single
//     per-tile __syncthreads().
//   - scores parked in a conflict-free per-thread SMEM column (stride NT) so
//     the online-softmax accumulator rescale happens once per tile.
//   - all hot-loop SMEM reads are float4 (LDS.128, broadcast across the warp).
//   - padding mask read as 32-bit words with a nonzero test: correct for both
//     int32 (0/1) and float32 (0.0/1.0) storage of the jax bool array.
__global__ __launch_bounds__(NT, 2)
void fa_fp32_kernel(const float* __restrict__ Q,
                    const float* __restrict__ K,
                    const float* __restrict__ V,
                    const float* __restrict__ AM,          // [1,1,S,S] additive
                    const unsigned int* __restrict__ PM,   // [B,S,S] bool as 4-byte
                    float* __restrict__ O)
{
    __shared__ float Ks[2][BN * DH];   // 2 x 8 KB
    __shared__ float Vs[2][BN * DH];   // 2 x 8 KB
    __shared__ float Ss[BN * NT];      // 16 KB, Ss[j*NT + tid]

    const int tid  = threadIdx.x;
    const int bh   = blockIdx.y;          // b*H + h
    const int b    = bh >> 4;             // H = 16
    const int qrow = blockIdx.x * BM + tid;

    const size_t base = (size_t)bh * SEQ * DH;

    // Query row, pre-scaled by 1/sqrt(64) = 0.125 exactly.
    const float4* qp = reinterpret_cast<const float4*>(Q + base + (size_t)qrow * DH);
    float4 qv[DH / 4];
#pragma unroll
    for (int i = 0; i < DH / 4; i++) {
        float4 t = qp[i];
        qv[i] = make_float4(t.x * 0.125f, t.y * 0.125f, t.z * 0.125f, t.w * 0.125f);
    }

    float4 acc[DH / 4];
#pragma unroll
    for (int i = 0; i < DH / 4; i++) acc[i] = make_float4(0.f, 0.f, 0.f, 0.f);

    // Large-finite sentinel instead of -inf: m/corr arithmetic never NaNs even
    // for a fully-masked tile; exp(-1e30 - m) flushes to 0 once a real max
    // appears, matching the -inf reference behavior.
    float m = -1e30f;
    float l = 0.f;

    const float*        amrow = AM + (size_t)qrow * SEQ;
    const unsigned int* pmrow = PM + ((size_t)b * SEQ + qrow) * SEQ;

    const float4* Kg = reinterpret_cast<const float4*>(K + base);
    const float4* Vg = reinterpret_cast<const float4*>(V + base);

    // ---- prologue: tile 0 straight into buffer 0 ----
    {
        float4* Ks4 = reinterpret_cast<float4*>(Ks[0]);
        float4* Vs4 = reinterpret_cast<float4*>(Vs[0]);
#pragma unroll
        for (int i = 0; i < (BN * DH / 4) / NT; i++) {    // 4 each
            Ks4[i * NT + tid] = Kg[i * NT + tid];
            Vs4[i * NT + tid] = Vg[i * NT + tid];
        }
    }
    __syncthreads();

    int cur = 0;
    for (int t = 0; t < NTILES; t++) {
        // ---- prefetch tile t+1 into registers (consumed after compute) ----
        float4 kpre[(BN * DH / 4) / NT];   // 4 x float4
        float4 vpre[(BN * DH / 4) / NT];
        const bool havenext = (t + 1 < NTILES);
        if (havenext) {
            const int toff = (t + 1) * (BN * DH / 4);
#pragma unroll
            for (int i = 0; i < (BN * DH / 4) / NT; i++) {
                kpre[i] = Kg[toff + i * NT + tid];
                vpre[i] = Vg[toff + i * NT + tid];
            }
        }

        // ---- scores for tile t ----
        const int col0 = t * BN;
        const float* Kc = Ks[cur];
        const float* Vc = Vs[cur];
        float tmax = -1e30f;
#pragma unroll 4
        for (int j = 0; j < BN; j++) {
            const float4* kr = reinterpret_cast<const float4*>(Kc + j * DH);
            float s0 = 0.f, s1 = 0.f, s2 = 0.f, s3 = 0.f;
#pragma unroll
            for (int d = 0; d < DH / 16; d++) {           // 4 iters x 4 float4
                float4 k0 = kr[d * 4 + 0];
                float4 k1 = kr[d * 4 + 1];
                float4 k2 = kr[d * 4 + 2];
                float4 k3 = kr[d * 4 + 3];
                s0 = fmaf(qv[d*4+0].w, k0.w, fmaf(qv[d*4+0].z, k0.z,
                     fmaf(qv[d*4+0].y, k0.y, fmaf(qv[d*4+0].x, k0.x, s0))));
                s1 = fmaf(qv[d*4+1].w, k1.w, fmaf(qv[d*4+1].z, k1.z,
                     fmaf(qv[d*4+1].y, k1.y, fmaf(qv[d*4+1].x, k1.x, s1))));
                s2 = fmaf(qv[d*4+2].w, k2.w, fmaf(qv[d*4+2].z, k2.z,
                     fmaf(qv[d*4+2].y, k2.y, fmaf(qv[d*4+2].x, k2.x, s2))));
                s3 = fmaf(qv[d*4+3].w, k3.w, fmaf(qv[d*4+3].z, k3.z,
                     fmaf(qv[d*4+3].y, k3.y, fmaf(qv[d*4+3].x, k3.x, s3))));
            }
            float s = (s0 + s1) + (s2 + s3);
            s += __ldg(amrow + col0 + j);                 // L1-resident after j=0
            if (__ldg(pmrow + col0 + j) != 0u) s = -1e30f;
            tmax = fmaxf(tmax, s);
            Ss[j * NT + tid] = s;                         // conflict-free column
        }

        // ---- online softmax update (once per tile) ----
        const float mnew = fmaxf(m, tmax);
        const float corr = __expf(m - mnew);
        m = mnew;
        l *= corr;
#pragma unroll
        for (int i = 0; i < DH / 4; i++) {
            acc[i].x *= corr; acc[i].y *= corr;
            acc[i].z *= corr; acc[i].w *= corr;
        }

        // ---- P @ V ----
#pragma unroll 2
        for (int j = 0; j < BN; j++) {
            const float p = __expf(Ss[j * NT + tid] - mnew);
            l += p;
            const float4* vr = reinterpret_cast<const float4*>(Vc + j * DH);
#pragma unroll
            for (int i = 0; i < DH / 4; i++) {
                float4 vv = vr[i];
                acc[i].x = fmaf(p, vv.x, acc[i].x);
                acc[i].y = fmaf(p, vv.y, acc[i].y);
                acc[i].z = fmaf(p, vv.z, acc[i].z);
                acc[i].w = fmaf(p, vv.w, acc[i].w);
            }
        }

        // ---- commit prefetched tile to the alternate buffer ----
        // Safe: buf cur^1 was last READ in iteration t-1, and the t-1 barrier
        // already separated those reads from these writes.
        if (havenext) {
            float4* Kn = reinterpret_cast<float4*>(Ks[cur ^ 1]);
            float4* Vn = reinterpret_cast<float4*>(Vs[cur ^ 1]);
#pragma unroll
            for (int i = 0; i < (BN * DH / 4) / NT; i++) {
                Kn[i * NT + tid] = kpre[i];
                Vn[i * NT + tid] = vpre[i];
            }
        }
        __syncthreads();
        cur ^= 1;
    }

    // ---- epilogue: normalize and store ----
    const float inv = 1.f / l;
    float4* op = reinterpret_cast<float4*>(O + base + (size_t)qrow * DH);
#pragma unroll
    for (int i = 0; i < DH / 4; i++)
        op[i] = make_float4(acc[i].x * inv, acc[i].y * inv,
                            acc[i].z * inv, acc[i].w * inv);
}

extern "C" void kernel_launch(void* const* d_in, const int* in_sizes, int n_in,
                              void* d_out, int out_size)
{
    // Expected metadata order: q, k, v, att_mask, padding_mask.
    // Hedge: identify the two masks by element count (att_mask = S*S = 4.2M,
    // padding_mask = B*S*S = 16.8M) so a different ordering can't break us.
    const float* q = (const float*)d_in[0];
    const float* k = (const float*)d_in[1];
    const float* v = (const float*)d_in[2];

    const void* m3 = d_in[3];
    const void* m4 = d_in[4];
    const float*        am;
    const unsigned int* pm;
    if (in_sizes[3] == SEQ * SEQ) {            // [1,1,S,S] additive mask first
        am = (const float*)m3;
        pm = (const unsigned int*)m4;
    } else {                                   // swapped
        am = (const float*)m4;
        pm = (const unsigned int*)m3;
    }
    float* out = (float*)d_out;

    dim3 grid(SEQ / BM, BATCH * HEADS);        // (16, 64)
    fa_fp32_kernel<<<grid, NT>>>(q, k, v, am, pm, out);
}

// round 5
// speedup vs baseline: 1.3515x; 1.3515x over previous
#include <cuda_runtime.h>
#include <cstdint>

// Problem shapes (fixed by the dataset)
#define BATCH 4
#define HEADS 16
#define SEQ   2048
#define DH    64       // head dim
#define BM    128      // query rows per CTA (= threads, 1 row/thread)
#define BN    32       // key/value tile size
#define NT    128      // threads per CTA
#define NTILES (SEQ / BN)
#define MST   (NT + 1) // padded stride for the mask/score buffer (conflict-free)

typedef unsigned long long ull;

// ---- packed f32x2 helpers (sm_100+) --------------------------------------
__device__ __forceinline__ ull pack2(float lo, float hi) {
    ull r; asm("mov.b64 %0,{%1,%2};" : "=l"(r) : "f"(lo), "f"(hi)); return r;
}
__device__ __forceinline__ void unpack2(ull v, float& lo, float& hi) {
    asm("mov.b64 {%0,%1},%2;" : "=f"(lo), "=f"(hi) : "l"(v));
}
__device__ __forceinline__ ull fma2(ull a, ull b, ull c) {
    ull d; asm("fma.rn.f32x2 %0,%1,%2,%3;" : "=l"(d) : "l"(a), "l"(b), "l"(c)); return d;
}
__device__ __forceinline__ ull mul2(ull a, ull b) {
    ull d; asm("mul.rn.f32x2 %0,%1,%2;" : "=l"(d) : "l"(a), "l"(b)); return d;
}

// Dynamic SMEM layout (floats):
//   Ks: [2][BN*DH]   (2 x 8 KB)
//   Vs: [2][BN*DH]   (2 x 8 KB)
//   Ms: [2][BN*MST]  (2 x 16.1 KB) combined-mask in / scores out, transposed+padded
#define SMEM_FLOATS (4 * BN * DH + 2 * BN * MST)

// Flash attention, fp32, one thread per query row.
// Key changes vs prior round (L1tex was 80% busy, 2/3 of it from per-thread
// scattered mask LDGs at 32 lines/instr):
//   * AM/PM tiles are loaded cooperatively (coalesced, 4 lines/LDG.128),
//     combined to a single additive value (pm ? -1e30 : am), and staged
//     TRANSPOSED into padded SMEM -> conflict-free scalar access by row.
//   * Scores overwrite the mask value in-place (one SMEM round-trip total).
//   * QK^T and P@V use packed fma.rn.f32x2 -> half the fma-pipe issue.
__global__ __launch_bounds__(NT, 2)
void fa_fp32_kernel(const float* __restrict__ Q,
                    const float* __restrict__ K,
                    const float* __restrict__ V,
                    const float* __restrict__ AM,          // [1,1,S,S] additive
                    const unsigned int* __restrict__ PM,   // [B,S,S] bool as 4-byte
                    float* __restrict__ O)
{
    extern __shared__ float smem[];
    float* Ks = smem;                    // [2][BN*DH]
    float* Vs = smem + 2 * BN * DH;      // [2][BN*DH]
    float* Ms = smem + 4 * BN * DH;      // [2][BN*MST]

    const int tid   = threadIdx.x;
    const int bh    = blockIdx.y;        // b*H + h
    const int b     = bh >> 4;           // H = 16
    const int qrow0 = blockIdx.x * BM;
    const int qrow  = qrow0 + tid;

    const size_t base = (size_t)bh * SEQ * DH;

    // ---- query row, packed and pre-scaled by 1/sqrt(64) = 0.125 ----
    const ull scale2 = pack2(0.125f, 0.125f);
    ull q2[DH / 2];                                   // 32 packed pairs
    {
        const ulonglong2* qp =
            reinterpret_cast<const ulonglong2*>(Q + base + (size_t)qrow * DH);
#pragma unroll
        for (int i = 0; i < DH / 4; i++) {
            ulonglong2 qq = qp[i];
            q2[2 * i + 0] = mul2(qq.x, scale2);
            q2[2 * i + 1] = mul2(qq.y, scale2);
        }
    }

    ull acc2[DH / 2];                                 // 32 packed pairs
#pragma unroll
    for (int i = 0; i < DH / 2; i++) acc2[i] = 0ull;  // {+0.f,+0.f}

    // Large-finite sentinel instead of -inf (no NaN propagation; exp of
    // (-1e30 - m) underflows to exactly 0, matching masked -inf behavior).
    float m = -1e30f;
    float l = 0.f;

    const float4* Kg = reinterpret_cast<const float4*>(K + base);
    const float4* Vg = reinterpret_cast<const float4*>(V + base);

    // ---- prologue: tile 0 (K/V + combined mask) into buffer 0 ----
    {
        float4* Ks4 = reinterpret_cast<float4*>(Ks);
        float4* Vs4 = reinterpret_cast<float4*>(Vs);
#pragma unroll
        for (int i = 0; i < (BN * DH / 4) / NT; i++) {     // 4 each
            Ks4[i * NT + tid] = Kg[i * NT + tid];
            Vs4[i * NT + tid] = Vg[i * NT + tid];
        }
        // mask tile 0: tasks tau = i*NT + tid; row = tau/8, idx = tau%8
#pragma unroll
        for (int i = 0; i < 8; i++) {
            const int tau = i * NT + tid;
            const int row = tau >> 3;
            const int idx = tau & 7;
            const float4 a = *reinterpret_cast<const float4*>(
                AM + (size_t)(qrow0 + row) * SEQ + idx * 4);
            const uint4 p = *reinterpret_cast<const uint4*>(
                PM + ((size_t)b * SEQ + (qrow0 + row)) * SEQ + idx * 4);
            const int col = idx * 4;
            Ms[(col + 0) * MST + row] = p.x ? -1e30f : a.x;
            Ms[(col + 1) * MST + row] = p.y ? -1e30f : a.y;
            Ms[(col + 2) * MST + row] = p.z ? -1e30f : a.z;
            Ms[(col + 3) * MST + row] = p.w ? -1e30f : a.w;
        }
    }
    __syncthreads();

    int cur = 0;
    for (int t = 0; t < NTILES; t++) {
        const int col0 = t * BN;

        // ---- prefetch tile t+1 into registers ----
        float4 kpre[4], vpre[4], cpre[8];
        const bool hn = (t + 1 < NTILES);
        if (hn) {
            const int toff = (t + 1) * (BN * DH / 4);
#pragma unroll
            for (int i = 0; i < 4; i++) {
                kpre[i] = Kg[toff + i * NT + tid];
                vpre[i] = Vg[toff + i * NT + tid];
            }
            const int ncol0 = col0 + BN;
#pragma unroll
            for (int i = 0; i < 8; i++) {
                const int tau = i * NT + tid;
                const int row = tau >> 3;
                const int idx = tau & 7;
                const float4 a = *reinterpret_cast<const float4*>(
                    AM + (size_t)(qrow0 + row) * SEQ + ncol0 + idx * 4);
                const uint4 p = *reinterpret_cast<const uint4*>(
                    PM + ((size_t)b * SEQ + (qrow0 + row)) * SEQ + ncol0 + idx * 4);
                cpre[i].x = p.x ? -1e30f : a.x;
                cpre[i].y = p.y ? -1e30f : a.y;
                cpre[i].z = p.z ? -1e30f : a.z;
                cpre[i].w = p.w ? -1e30f : a.w;
            }
        }

        const float* Kc = Ks + cur * (BN * DH);
        const float* Vc = Vs + cur * (BN * DH);
        float*       Mc = Ms + cur * (BN * MST);

        // ---- scores: packed dot + staged mask, written back in-place ----
        float tmax = -1e30f;
#pragma unroll 4
        for (int j = 0; j < BN; j++) {
            const ulonglong2* kr =
                reinterpret_cast<const ulonglong2*>(Kc + j * DH);
            ull sa = 0ull, sb = 0ull, sc = 0ull, sd = 0ull;
#pragma unroll
            for (int dd = 0; dd < 8; dd++) {              // 16 LDS.128
                ulonglong2 k0 = kr[2 * dd + 0];
                ulonglong2 k1 = kr[2 * dd + 1];
                sa = fma2(q2[4 * dd + 0], k0.x, sa);
                sb = fma2(q2[4 * dd + 1], k0.y, sb);
                sc = fma2(q2[4 * dd + 2], k1.x, sc);
                sd = fma2(q2[4 * dd + 3], k1.y, sd);
            }
            float x0, x1, x2, x3, x4, x5, x6, x7;
            unpack2(sa, x0, x1); unpack2(sb, x2, x3);
            unpack2(sc, x4, x5); unpack2(sd, x6, x7);
            float s = ((x0 + x1) + (x2 + x3)) + ((x4 + x5) + (x6 + x7));
            s += Mc[j * MST + tid];                       // combined mask
            tmax = fmaxf(tmax, s);
            Mc[j * MST + tid] = s;                        // score, in place
        }

        // ---- commit K + mask prefetch to alternate buffer (frees regs) ----
        if (hn) {
            float4* Kn4 = reinterpret_cast<float4*>(Ks + (cur ^ 1) * (BN * DH));
#pragma unroll
            for (int i = 0; i < 4; i++) Kn4[i * NT + tid] = kpre[i];
            float* Mn = Ms + (cur ^ 1) * (BN * MST);
#pragma unroll
            for (int i = 0; i < 8; i++) {
                const int tau = i * NT + tid;
                const int row = tau >> 3;
                const int col = (tau & 7) * 4;
                Mn[(col + 0) * MST + row] = cpre[i].x;
                Mn[(col + 1) * MST + row] = cpre[i].y;
                Mn[(col + 2) * MST + row] = cpre[i].z;
                Mn[(col + 3) * MST + row] = cpre[i].w;
            }
        }

        // ---- online softmax update (once per tile) ----
        const float mnew = fmaxf(m, tmax);
        const float corr = __expf(m - mnew);
        m = mnew;
        l *= corr;
        const ull cc = pack2(corr, corr);
#pragma unroll
        for (int i = 0; i < DH / 2; i++) acc2[i] = mul2(acc2[i], cc);

        // ---- P @ V (packed) ----
#pragma unroll 2
        for (int j = 0; j < BN; j++) {
            const float p = __expf(Mc[j * MST + tid] - mnew);
            l += p;
            const ull pp = pack2(p, p);
            const ulonglong2* vr =
                reinterpret_cast<const ulonglong2*>(Vc + j * DH);
#pragma unroll
            for (int dd = 0; dd < DH / 4; dd++) {         // 16 LDS.128
                ulonglong2 vv = vr[dd];
                acc2[2 * dd + 0] = fma2(pp, vv.x, acc2[2 * dd + 0]);
                acc2[2 * dd + 1] = fma2(pp, vv.y, acc2[2 * dd + 1]);
            }
        }

        // ---- commit V prefetch ----
        if (hn) {
            float4* Vn4 = reinterpret_cast<float4*>(Vs + (cur ^ 1) * (BN * DH));
#pragma unroll
            for (int i = 0; i < 4; i++) Vn4[i * NT + tid] = vpre[i];
        }
        __syncthreads();
        cur ^= 1;
    }

    // ---- epilogue: normalize and store ----
    const float inv = 1.f / l;
    const ull iv = pack2(inv, inv);
    ulonglong2* op =
        reinterpret_cast<ulonglong2*>(O + base + (size_t)qrow * DH);
#pragma unroll
    for (int i = 0; i < DH / 4; i++) {
        ulonglong2 o;
        o.x = mul2(acc2[2 * i + 0], iv);
        o.y = mul2(acc2[2 * i + 1], iv);
        op[i] = o;
    }
}

extern "C" void kernel_launch(void* const* d_in, const int* in_sizes, int n_in,
                              void* d_out, int out_size)
{
    // Expected metadata order: q, k, v, att_mask, padding_mask.
    // Identify the two masks by element count so ordering can't break us:
    //   att_mask = S*S = 4,194,304 ; padding_mask = B*S*S = 16,777,216.
    const float* q = (const float*)d_in[0];
    const float* k = (const float*)d_in[1];
    const float* v = (const float*)d_in[2];

    const float*        am;
    const unsigned int* pm;
    if (in_sizes[3] == SEQ * SEQ) {
        am = (const float*)d_in[3];
        pm = (const unsigned int*)d_in[4];
    } else {
        am = (const float*)d_in[4];
        pm = (const unsigned int*)d_in[3];
    }
    float* out = (float*)d_out;

    const int smem_bytes = SMEM_FLOATS * (int)sizeof(float);   // ~64.3 KB
    cudaFuncSetAttribute(fa_fp32_kernel,
                         cudaFuncAttributeMaxDynamicSharedMemorySize,
                         smem_bytes);

    dim3 grid(SEQ / BM, BATCH * HEADS);        // (16, 64)
    fa_fp32_kernel<<<grid, NT, smem_bytes>>>(q, k, v, am, pm, out);
}